// round 16
// baseline (speedup 1.0000x reference)
#include <cuda_runtime.h>

typedef unsigned long long ull;

// Chain state. h1 ping-pong (launch j reads [j&1], writes [(j+1)&1]), h2 per block.
__device__ float g_h1[2][16][4][64][64];   //  2.1 MB
__device__ float g_h2[32][16][4][64][64];  // 33.6 MB

// ---- packed fp32x2 helpers --------------------------------------------------
__device__ __forceinline__ ull ffma2(ull a, ull b, ull c) {
    ull d; asm("fma.rn.f32x2 %0, %1, %2, %3;" : "=l"(d) : "l"(a), "l"(b), "l"(c)); return d;
}
__device__ __forceinline__ ull pack2(float lo, float hi) {
    ull d; asm("mov.b64 %0, {%1, %2};" : "=l"(d) : "f"(lo), "f"(hi)); return d;
}
__device__ __forceinline__ ull dup2(float v) { return pack2(v, v); }
__device__ __forceinline__ ull relu2(ull z) {
    float lo, hi; asm("mov.b64 {%0, %1}, %2;" : "=f"(lo), "=f"(hi) : "l"(z));
    return pack2(fmaxf(lo, 0.f), fmaxf(hi, 0.f));
}
__device__ __forceinline__ ull fadd2(ull a, ull b) {
    ull d; asm("add.rn.f32x2 %0, %1, %2;" : "=l"(d) : "l"(a), "l"(b)); return d;
}
__device__ __forceinline__ ull packmid(ull a, ull b) {
    float alo, ahi, blo, bhi;
    asm("mov.b64 {%0, %1}, %2;" : "=f"(alo), "=f"(ahi) : "l"(a));
    asm("mov.b64 {%0, %1}, %2;" : "=f"(blo), "=f"(bhi) : "l"(b));
    return pack2(ahi, blo);
}
__device__ __forceinline__ void unpack2(ull v, float& lo, float& hi) {
    asm("mov.b64 {%0, %1}, %2;" : "=f"(lo), "=f"(hi) : "l"(v));
}

// ---------------------------------------------------------------------------
// k0: h1_0 = relu(W1_0 @ x + b1_0).  Memory-bound (reads x, 67MB).
// ---------------------------------------------------------------------------
__global__ __launch_bounds__(256) void k0_kernel(const float* __restrict__ x,
                                                 const float* __restrict__ w1,
                                                 const float* __restrict__ b1) {
    __shared__ float4 sW1T[256];
    __shared__ float  sB1[4];
    int tid = threadIdx.x;
    if (tid < 4) sB1[tid] = b1[tid];
    sW1T[tid] = make_float4(w1[tid], w1[256 + tid], w1[512 + tid], w1[768 + tid]);
    __syncthreads();

    int n  = blockIdx.x >> 4;
    int yg = blockIdx.x & 15;
    int px = tid & 63;
    int y  = yg * 4 + (tid >> 6);

    const float* xp = x + (size_t)n * 256 * 4096 + y * 64 + px;
    float a0 = sB1[0], a1 = sB1[1], a2 = sB1[2], a3 = sB1[3];
#pragma unroll 8
    for (int c = 0; c < 256; c++) {
        float  xv = xp[c * 4096];
        float4 w  = sW1T[c];
        a0 = fmaf(xv, w.x, a0);
        a1 = fmaf(xv, w.y, a1);
        a2 = fmaf(xv, w.z, a2);
        a3 = fmaf(xv, w.w, a3);
    }
    float* hp = &g_h1[0][n][0][y][px];
    hp[0]     = fmaxf(a0, 0.f);
    hp[4096]  = fmaxf(a1, 0.f);
    hp[8192]  = fmaxf(a2, 0.f);
    hp[12288] = fmaxf(a3, 0.f);
}

// ---------------------------------------------------------------------------
// fused core: 4 pixels (linear p0..p0+3 in u-arrays) through 64 channels
// (quarter q of channel pairs, conflict-free [mm][q] layout), returns
// res[px][j] = quarter-reduced (via 2 butterfly shuffles) channel sums.
// ---------------------------------------------------------------------------
__device__ __forceinline__ void fused_core(
    const float* __restrict__ u0r, const float* __restrict__ u1r,
    const float* __restrict__ u2r, const float* __restrict__ u3r,
    int p0, int q,
    const ulonglong2 (*__restrict__ w3p)[4][2],
    const ulonglong2 (*__restrict__ w1p)[4][2],
    const ull (*__restrict__ b3p)[4],
    float res[4][4])
{
    float4 uu0 = *(const float4*)(u0r + p0);
    float4 uu1 = *(const float4*)(u1r + p0);
    float4 uu2 = *(const float4*)(u2r + p0);
    float4 uu3 = *(const float4*)(u3r + p0);

    ull ud[4][4];
    ud[0][0] = dup2(uu0.x); ud[0][1] = dup2(uu1.x); ud[0][2] = dup2(uu2.x); ud[0][3] = dup2(uu3.x);
    ud[1][0] = dup2(uu0.y); ud[1][1] = dup2(uu1.y); ud[1][2] = dup2(uu2.y); ud[1][3] = dup2(uu3.y);
    ud[2][0] = dup2(uu0.z); ud[2][1] = dup2(uu1.z); ud[2][2] = dup2(uu2.z); ud[2][3] = dup2(uu3.z);
    ud[3][0] = dup2(uu0.w); ud[3][1] = dup2(uu1.w); ud[3][2] = dup2(uu2.w); ud[3][3] = dup2(uu3.w);

    ull ap[4][4];
#pragma unroll
    for (int k2 = 0; k2 < 4; k2++)
#pragma unroll
        for (int j = 0; j < 4; j++) ap[k2][j] = 0ull;

#pragma unroll 4
    for (int mm = 0; mm < 32; mm++) {
        ulonglong2 w3a = w3p[mm][q][0], w3b = w3p[mm][q][1];
        ulonglong2 w1a = w1p[mm][q][0], w1b = w1p[mm][q][1];
        ull bb = b3p[mm][q];
#pragma unroll
        for (int k2 = 0; k2 < 4; k2++) {
            ull z = ffma2(ud[k2][0], w3a.x, bb);
            z = ffma2(ud[k2][1], w3a.y, z);
            z = ffma2(ud[k2][2], w3b.x, z);
            z = ffma2(ud[k2][3], w3b.y, z);
            ull v = relu2(z);
            ap[k2][0] = ffma2(v, w1a.x, ap[k2][0]);
            ap[k2][1] = ffma2(v, w1a.y, ap[k2][1]);
            ap[k2][2] = ffma2(v, w1b.x, ap[k2][2]);
            ap[k2][3] = ffma2(v, w1b.y, ap[k2][3]);
        }
    }

#pragma unroll
    for (int k2 = 0; k2 < 4; k2++) {
#pragma unroll
        for (int j = 0; j < 4; j++) {
            float lo, hi;
            asm("mov.b64 {%0, %1}, %2;" : "=f"(lo), "=f"(hi) : "l"(ap[k2][j]));
            float r = lo + hi;
            r += __shfl_xor_sync(0xffffffffu, r, 1);
            r += __shfl_xor_sync(0xffffffffu, r, 2);
            res[k2][j] = r;
        }
    }
}

// ---------------------------------------------------------------------------
// chain2_kernel: TWO chain steps per launch (blocks blk, blk+1).
//   grid 256 = 16 img x 16 tiles (16x16 final). 256 threads.
//   Step 1 runs on an 18x18 halo-extended region (13% redundant, identical
//   across CTAs); h1_{blk+1} lives only in smem. Step 2 on the 16x16 tile.
//   rd = read buffer of g_h1; writes (blk+2) into rd^1 (skipped for blk=30).
//   NOTE: step-1 h2 stores use SCALAR STG (pair centers are at odd gx — an
//   8-byte store there traps with misaligned address).
// ---------------------------------------------------------------------------
__global__ __launch_bounds__(256, 2) void chain2_kernel(
    const float* __restrict__ w1, const float* __restrict__ b1,
    const float* __restrict__ w2, const float* __restrict__ b2,
    const float* __restrict__ w3, const float* __restrict__ b3,
    int blk, int rd)
{
    __shared__ __align__(16) float s_h1a[4][20][20];   // h1_blk halo region
    __shared__ __align__(16) float s_h1b[4][18][18];   // h1_{blk+1} (local only)
    __shared__ __align__(16) float s_ua[4][324];       // conv output (reused)
    __shared__ ull        s_w2d[2][144];               // dup-packed conv weights
    __shared__ float      s_b2[2][4];
    __shared__ ulonglong2 s_w3p[2][32][4][2];          // channel-pair packed
    __shared__ ulonglong2 s_w1p[2][32][4][2];
    __shared__ ull        s_b3p[2][32][4];
    __shared__ float      s_b1n[2][4];

    int tid  = threadIdx.x;
    int n    = blockIdx.x >> 4;
    int tile = blockIdx.x & 15;
    int ty0  = (tile >> 2) * 16;
    int tx0  = (tile & 3)  * 16;

    // ---- weight staging (both steps) ----
    for (int idx = tid; idx < 288; idx += 256) {
        int set = idx / 144, w = idx - set * 144;
        s_w2d[set][w] = dup2(w2[(blk + set) * 144 + w]);
    }
    if (tid < 8) s_b2[tid >> 2][tid & 3] = b2[(blk + (tid >> 2)) * 4 + (tid & 3)];
    else if (tid < 16) {
        int k = tid - 8, set = k >> 2;
        if (set == 0 || blk < 30)
            s_b1n[set][k & 3] = b1[(blk + 1 + set) * 4 + (k & 3)];
    }
    {
        int set = tid >> 7;            // 0 or 1
        int m   = tid & 127;           // channel pair index
        int mm  = m >> 2, qs = m & 3;
        int bW3 = blk + set;           // w3/b3 block (<=31, valid)
        const float* w3r = &w3[((size_t)bW3 * 256 + 2 * m) * 4];
        float4 ra = *(const float4*)w3r;
        float4 rb = *(const float4*)(w3r + 4);
        s_w3p[set][mm][qs][0] = make_ulonglong2(pack2(ra.x, rb.x), pack2(ra.y, rb.y));
        s_w3p[set][mm][qs][1] = make_ulonglong2(pack2(ra.z, rb.z), pack2(ra.w, rb.w));
        s_b3p[set][mm][qs] = pack2(b3[bW3 * 256 + 2 * m], b3[bW3 * 256 + 2 * m + 1]);
        int bW1 = blk + 1 + set;       // w1 block (invalid only when set=1, blk=30)
        if (set == 0 || blk < 30) {
            const float* w1n = w1 + bW1 * 1024;
            s_w1p[set][mm][qs][0] = make_ulonglong2(pack2(w1n[2 * m],       w1n[2 * m + 1]),
                                                    pack2(w1n[256 + 2 * m], w1n[256 + 2 * m + 1]));
            s_w1p[set][mm][qs][1] = make_ulonglong2(pack2(w1n[512 + 2 * m], w1n[512 + 2 * m + 1]),
                                                    pack2(w1n[768 + 2 * m], w1n[768 + 2 * m + 1]));
        }
    }

    // ---- halo load: h1_blk on 20x20 (zero pad outside image) ----
    const float* h1base = &g_h1[rd][n][0][0][0];
    for (int idx = tid; idx < 400; idx += 256) {
        int yy = idx / 20, xx = idx % 20;
        int gy = ty0 - 2 + yy, gx = tx0 - 2 + xx;
        bool ok = (gy >= 0 && gy < 64 && gx >= 0 && gx < 64);
#pragma unroll
        for (int k = 0; k < 4; k++)
            s_h1a[k][yy][xx] = ok ? h1base[k * 4096 + gy * 64 + gx] : 0.f;
    }
    __syncthreads();

    // =========================== STEP 1 (block blk) ==========================
    // conv on 18x18 region; region px (ry,rx) = s_h1a coords (ry+1, rx+1);
    // 162 pixel-pairs; store h2_blk (scalar, bounds-checked); u -> s_ua.
    if (tid < 162) {
        int p   = tid;
        int ry  = p / 9;
        int rx  = (p - ry * 9) * 2;
        ull r0 = dup2(s_b2[0][0]), r1 = dup2(s_b2[0][1]);
        ull r2 = dup2(s_b2[0][2]), r3 = dup2(s_b2[0][3]);
#pragma unroll
        for (int k = 0; k < 4; k++) {
#pragma unroll
            for (int dy = 0; dy < 3; dy++) {
                const ull* rowp = (const ull*)&s_h1a[k][ry + dy][rx];
                ull p01 = rowp[0], p23 = rowp[1];
                ull t0 = p01, t1 = packmid(p01, p23), t2 = p23;
                int wi = k * 9 + dy * 3;
                r0 = ffma2(t0, s_w2d[0][wi + 0], r0);
                r1 = ffma2(t0, s_w2d[0][36 + wi + 0], r1);
                r2 = ffma2(t0, s_w2d[0][72 + wi + 0], r2);
                r3 = ffma2(t0, s_w2d[0][108 + wi + 0], r3);
                r0 = ffma2(t1, s_w2d[0][wi + 1], r0);
                r1 = ffma2(t1, s_w2d[0][36 + wi + 1], r1);
                r2 = ffma2(t1, s_w2d[0][72 + wi + 1], r2);
                r3 = ffma2(t1, s_w2d[0][108 + wi + 1], r3);
                r0 = ffma2(t2, s_w2d[0][wi + 2], r0);
                r1 = ffma2(t2, s_w2d[0][36 + wi + 2], r1);
                r2 = ffma2(t2, s_w2d[0][72 + wi + 2], r2);
                r3 = ffma2(t2, s_w2d[0][108 + wi + 2], r3);
            }
        }
        ull u0 = relu2(r0), u1 = relu2(r1), u2 = relu2(r2), u3 = relu2(r3);

        *(ull*)&s_ua[0][2 * p] = u0;
        *(ull*)&s_ua[1][2 * p] = u1;
        *(ull*)&s_ua[2][2 * p] = u2;
        *(ull*)&s_ua[3][2 * p] = u3;

        // h2_blk store — SCALAR (pair centers at odd gx; duplicate stores
        // from neighbor CTAs are bitwise-identical -> benign)
        int gy = ty0 - 1 + ry, gx = tx0 - 1 + rx;
        if (gy >= 0 && gy < 64) {
            float lo0, hi0, lo1, hi1, lo2, hi2, lo3, hi3;
            unpack2(u0, lo0, hi0); unpack2(u1, lo1, hi1);
            unpack2(u2, lo2, hi2); unpack2(u3, lo3, hi3);
            float* hb = &g_h2[blk][n][0][gy][0];
            if (gx >= 0 && gx < 64) {
                hb[gx] = lo0; hb[4096 + gx] = lo1;
                hb[8192 + gx] = lo2; hb[12288 + gx] = lo3;
            }
            int gx1 = gx + 1;
            if (gx1 >= 0 && gx1 < 64) {
                hb[gx1] = hi0; hb[4096 + gx1] = hi1;
                hb[8192 + gx1] = hi2; hb[12288 + gx1] = hi3;
            }
        }
    }
    __syncthreads();

    // fused step 1: 324 px in two waves of 64 slots (4 px each); out -> s_h1b
    {
        int slot = tid >> 2;
        int q    = tid & 3;
        float bq = s_b1n[0][q];
#pragma unroll
        for (int w = 0; w < 2; w++) {
            int s0 = slot + w * 64;
            bool active = (s0 < 81);
            int sC = active ? s0 : 80;
            int p0 = sC * 4;
            float res[4][4];
            fused_core(&s_ua[0][0], &s_ua[1][0], &s_ua[2][0], &s_ua[3][0],
                       p0, q, s_w3p[0], s_w1p[0], s_b3p[0], res);
            if (active) {
#pragma unroll
                for (int e = 0; e < 4; e++) {
                    int px = p0 + e;
                    int ry = px / 18, rx = px - ry * 18;
                    int gy = ty0 - 1 + ry, gx = tx0 - 1 + rx;
                    bool in = (gy >= 0 && gy < 64 && gx >= 0 && gx < 64);
                    s_h1b[q][ry][rx] = in ? fmaxf(res[e][q] + bq, 0.f) : 0.f;
                }
            }
        }
    }
    __syncthreads();

    // =========================== STEP 2 (block blk+1) ========================
    // conv on the 16x16 tile; 128 pairs (even-aligned); store h2_{blk+1}.
    if (tid < 128) {
        int pair = tid;
        int py = pair >> 3;
        int x0 = (pair & 7) * 2;
        ull r0 = dup2(s_b2[1][0]), r1 = dup2(s_b2[1][1]);
        ull r2 = dup2(s_b2[1][2]), r3 = dup2(s_b2[1][3]);
#pragma unroll
        for (int k = 0; k < 4; k++) {
#pragma unroll
            for (int dy = 0; dy < 3; dy++) {
                const ull* rowp = (const ull*)&s_h1b[k][py + dy][x0];
                ull p01 = rowp[0], p23 = rowp[1];
                ull t0 = p01, t1 = packmid(p01, p23), t2 = p23;
                int wi = k * 9 + dy * 3;
                r0 = ffma2(t0, s_w2d[1][wi + 0], r0);
                r1 = ffma2(t0, s_w2d[1][36 + wi + 0], r1);
                r2 = ffma2(t0, s_w2d[1][72 + wi + 0], r2);
                r3 = ffma2(t0, s_w2d[1][108 + wi + 0], r3);
                r0 = ffma2(t1, s_w2d[1][wi + 1], r0);
                r1 = ffma2(t1, s_w2d[1][36 + wi + 1], r1);
                r2 = ffma2(t1, s_w2d[1][72 + wi + 1], r2);
                r3 = ffma2(t1, s_w2d[1][108 + wi + 1], r3);
                r0 = ffma2(t2, s_w2d[1][wi + 2], r0);
                r1 = ffma2(t2, s_w2d[1][36 + wi + 2], r1);
                r2 = ffma2(t2, s_w2d[1][72 + wi + 2], r2);
                r3 = ffma2(t2, s_w2d[1][108 + wi + 2], r3);
            }
        }
        ull u0 = relu2(r0), u1 = relu2(r1), u2 = relu2(r2), u3 = relu2(r3);

        *(ull*)&s_ua[0][2 * pair] = u0;
        *(ull*)&s_ua[1][2 * pair] = u1;
        *(ull*)&s_ua[2][2 * pair] = u2;
        *(ull*)&s_ua[3][2 * pair] = u3;

        int gy = ty0 + py, gx = tx0 + x0;        // gx even -> 8B aligned
        ull* hp = (ull*)&g_h2[blk + 1][n][0][gy][gx];
        hp[0] = u0; hp[2048] = u1; hp[4096] = u2; hp[6144] = u3;
    }
    __syncthreads();

    // fused step 2 -> h1_{blk+2} to gmem (skip on last launch)
    if (blk < 30) {
        int slot = tid >> 2;
        int q    = tid & 3;
        int p0   = slot * 4;
        float res[4][4];
        fused_core(&s_ua[0][0], &s_ua[1][0], &s_ua[2][0], &s_ua[3][0],
                   p0, q, s_w3p[1], s_w1p[1], s_b3p[1], res);
        float bq = s_b1n[1][q];
        int row = slot >> 2;
        int colb = (slot & 3) * 4;
        float* hp = &g_h1[rd ^ 1][n][q][ty0 + row][tx0 + colb];
        float4 o;
        o.x = fmaxf(res[0][q] + bq, 0.f);
        o.y = fmaxf(res[1][q] + bq, 0.f);
        o.z = fmaxf(res[2][q] + bq, 0.f);
        o.w = fmaxf(res[3][q] + bq, 0.f);
        *(float4*)hp = o;
    }
}

// ---------------------------------------------------------------------------
// acc_kernel: out = sum_i relu(W3_i @ h2_i + b3_i)  (R13 skewed form)
// ---------------------------------------------------------------------------
__global__ __launch_bounds__(256) void acc_kernel(const float* __restrict__ w3,
                                                  const float* __restrict__ b3,
                                                  float* __restrict__ out) {
    __shared__ ulonglong2 s_w3d[272][2];   // skewed: idx = c + (c>>4)
    __shared__ ull        s_b3d[272];
    __shared__ __align__(16) float s_u[4][64];

    int tid   = threadIdx.x;
    int n     = blockIdx.x >> 6;
    int y     = blockIdx.x & 63;
    int dual  = tid & 15;
    int grp   = tid >> 4;
    int pxA   = dual * 2;
    int pxB   = pxA + 32;
    int cbase = grp * 16;

    ull accA[16], accB[16];
#pragma unroll
    for (int cc = 0; cc < 16; cc++) { accA[cc] = 0ull; accB[cc] = 0ull; }

    for (int i = 0; i < 32; i++) {
        __syncthreads();
        float4 wr = *(const float4*)&w3[(i * 256 + tid) * 4];
        int sk = tid + (tid >> 4);
        s_w3d[sk][0] = make_ulonglong2(dup2(wr.x), dup2(wr.y));
        s_w3d[sk][1] = make_ulonglong2(dup2(wr.z), dup2(wr.w));
        s_b3d[sk]    = dup2(b3[i * 256 + tid]);
        s_u[tid >> 6][tid & 63] = g_h2[i][n][tid >> 6][y][tid & 63];
        __syncthreads();

        ull uA0 = *(const ull*)&s_u[0][pxA];
        ull uA1 = *(const ull*)&s_u[1][pxA];
        ull uA2 = *(const ull*)&s_u[2][pxA];
        ull uA3 = *(const ull*)&s_u[3][pxA];
        ull uB0 = *(const ull*)&s_u[0][pxB];
        ull uB1 = *(const ull*)&s_u[1][pxB];
        ull uB2 = *(const ull*)&s_u[2][pxB];
        ull uB3 = *(const ull*)&s_u[3][pxB];
        int skbase = cbase + grp;
#pragma unroll
        for (int cc = 0; cc < 16; cc++) {
            int c = skbase + cc;
            ulonglong2 wA = s_w3d[c][0], wB = s_w3d[c][1];
            ull bb = s_b3d[c];
            ull zA = ffma2(uA0, wA.x, bb);
            zA = ffma2(uA1, wA.y, zA);
            zA = ffma2(uA2, wB.x, zA);
            zA = ffma2(uA3, wB.y, zA);
            accA[cc] = fadd2(accA[cc], relu2(zA));
            ull zB = ffma2(uB0, wA.x, bb);
            zB = ffma2(uB1, wA.y, zB);
            zB = ffma2(uB2, wB.x, zB);
            zB = ffma2(uB3, wB.y, zB);
            accB[cc] = fadd2(accB[cc], relu2(zB));
        }
    }

#pragma unroll
    for (int cc = 0; cc < 16; cc++) {
        int c = cbase + cc;
        size_t base = (((size_t)n * 256 + c) * 64 + y) * 64;
        *(ull*)&out[base + pxA] = accA[cc];
        *(ull*)&out[base + pxB] = accB[cc];
    }
}

// ---------------------------------------------------------------------------
extern "C" void kernel_launch(void* const* d_in, const int* in_sizes, int n_in,
                              void* d_out, int out_size) {
    const float* x  = (const float*)d_in[0];
    const float* w1 = (const float*)d_in[1];
    const float* b1 = (const float*)d_in[2];
    const float* w2 = (const float*)d_in[3];
    const float* b2 = (const float*)d_in[4];
    const float* w3 = (const float*)d_in[5];
    const float* b3 = (const float*)d_in[6];
    float* out = (float*)d_out;

    k0_kernel<<<256, 256>>>(x, w1, b1);
    for (int j = 0; j < 16; j++)
        chain2_kernel<<<256, 256>>>(w1, b1, w2, b2, w3, b3, 2 * j, j & 1);
    acc_kernel<<<1024, 256>>>(w3, b3, out);
}